// round 9
// baseline (speedup 1.0000x reference)
#include <cuda_runtime.h>
#include <cuda_bf16.h>
#include <cstdint>

// x:   [B=64, C=12, 224, 224] fp32
// w:   [C=12, E=768] fp32
// out: [B=64, P=196, E=768] fp32
//
// CTA = 2x2 patch block x 2 batches (2 x 48 KB of x).
// Phase 1: warp = channel; two back-to-back rounds of 8 independent
//          full-line float4 loads (R7's proven staging), reduce to
//          pooled[12][8].
// Phase 2: each thread loads w[:, e4] once and emits FOUR patch outputs
//          (2 patch cols x 2 batches) -> w L1 traffic halved vs R7.

#define IMG    224
#define NP     14
#define C_IN   12
#define EMBED  768
#define NTH    384
#define BSTRIDE ((size_t)C_IN * IMG * IMG)   // floats between batches

__global__ __launch_bounds__(NTH, 3) void patch_block2_kernel(
    const float* __restrict__ x,
    const float* __restrict__ w,
    float* __restrict__ out)
{
    const int pp  = blockIdx.x;        // patch-col pair 0..6
    const int pr  = blockIdx.y;        // patch-row pair 0..6
    const int bz  = blockIdx.z;        // batch pair 0..31
    const int t   = threadIdx.x;
    const int warp = t >> 5;           // channel 0..11
    const int lane = t & 31;
    const int q8  = lane & 7;          // float4 col within the 32-float row
    const int rh  = lane >> 3;         // row phase 0..3

    __shared__ float pooled[C_IN][8];  // [channel][batch*4 + prow*2 + pcol]

    const float* base = x
        + (((size_t)((2 * bz) * C_IN + warp)) * IMG + (size_t)pr * 32 + rh) * IMG
        + (size_t)pp * 32 + q8 * 4;

    // ---- Phase 1, round 0 (batch 2*bz): 8 independent LDG.128 ----
    {
        float4 u0 = *reinterpret_cast<const float4*>(base + (size_t)(4 * 0) * IMG);
        float4 u1 = *reinterpret_cast<const float4*>(base + (size_t)(4 * 1) * IMG);
        float4 u2 = *reinterpret_cast<const float4*>(base + (size_t)(4 * 2) * IMG);
        float4 u3 = *reinterpret_cast<const float4*>(base + (size_t)(4 * 3) * IMG);
        float4 d0 = *reinterpret_cast<const float4*>(base + (size_t)(4 * 4) * IMG);
        float4 d1 = *reinterpret_cast<const float4*>(base + (size_t)(4 * 5) * IMG);
        float4 d2 = *reinterpret_cast<const float4*>(base + (size_t)(4 * 6) * IMG);
        float4 d3 = *reinterpret_cast<const float4*>(base + (size_t)(4 * 7) * IMG);

        float st = (((u0.x + u0.y) + (u0.z + u0.w)) + ((u1.x + u1.y) + (u1.z + u1.w)))
                 + (((u2.x + u2.y) + (u2.z + u2.w)) + ((u3.x + u3.y) + (u3.z + u3.w)));
        float sb = (((d0.x + d0.y) + (d0.z + d0.w)) + ((d1.x + d1.y) + (d1.z + d1.w)))
                 + (((d2.x + d2.y) + (d2.z + d2.w)) + ((d3.x + d3.y) + (d3.z + d3.w)));

        st += __shfl_xor_sync(0xffffffffu, st, 1);
        sb += __shfl_xor_sync(0xffffffffu, sb, 1);
        st += __shfl_xor_sync(0xffffffffu, st, 2);
        sb += __shfl_xor_sync(0xffffffffu, sb, 2);
        st += __shfl_xor_sync(0xffffffffu, st, 8);
        sb += __shfl_xor_sync(0xffffffffu, sb, 8);
        st += __shfl_xor_sync(0xffffffffu, st, 16);
        sb += __shfl_xor_sync(0xffffffffu, sb, 16);

        if ((lane & 27) == 0) {
            const int pc = (lane >> 2) & 1;
            pooled[warp][pc]     = st;
            pooled[warp][2 + pc] = sb;
        }
    }

    // ---- Phase 1, round 1 (batch 2*bz+1) ----
    {
        const float* b1 = base + BSTRIDE;
        float4 u0 = *reinterpret_cast<const float4*>(b1 + (size_t)(4 * 0) * IMG);
        float4 u1 = *reinterpret_cast<const float4*>(b1 + (size_t)(4 * 1) * IMG);
        float4 u2 = *reinterpret_cast<const float4*>(b1 + (size_t)(4 * 2) * IMG);
        float4 u3 = *reinterpret_cast<const float4*>(b1 + (size_t)(4 * 3) * IMG);
        float4 d0 = *reinterpret_cast<const float4*>(b1 + (size_t)(4 * 4) * IMG);
        float4 d1 = *reinterpret_cast<const float4*>(b1 + (size_t)(4 * 5) * IMG);
        float4 d2 = *reinterpret_cast<const float4*>(b1 + (size_t)(4 * 6) * IMG);
        float4 d3 = *reinterpret_cast<const float4*>(b1 + (size_t)(4 * 7) * IMG);

        float st = (((u0.x + u0.y) + (u0.z + u0.w)) + ((u1.x + u1.y) + (u1.z + u1.w)))
                 + (((u2.x + u2.y) + (u2.z + u2.w)) + ((u3.x + u3.y) + (u3.z + u3.w)));
        float sb = (((d0.x + d0.y) + (d0.z + d0.w)) + ((d1.x + d1.y) + (d1.z + d1.w)))
                 + (((d2.x + d2.y) + (d2.z + d2.w)) + ((d3.x + d3.y) + (d3.z + d3.w)));

        st += __shfl_xor_sync(0xffffffffu, st, 1);
        sb += __shfl_xor_sync(0xffffffffu, sb, 1);
        st += __shfl_xor_sync(0xffffffffu, st, 2);
        sb += __shfl_xor_sync(0xffffffffu, sb, 2);
        st += __shfl_xor_sync(0xffffffffu, st, 8);
        sb += __shfl_xor_sync(0xffffffffu, sb, 8);
        st += __shfl_xor_sync(0xffffffffu, st, 16);
        sb += __shfl_xor_sync(0xffffffffu, sb, 16);

        if ((lane & 27) == 0) {
            const int pc = (lane >> 2) & 1;
            pooled[warp][4 + pc] = st;
            pooled[warp][6 + pc] = sb;
        }
    }
    __syncthreads();

    // ---- Phase 2: one w column read serves four patch outputs ----
    const int e4 = t % 192;            // output float4 slot
    const int lr = t / 192;            // local patch row 0/1 (uniform per warp)

    float4 a00 = make_float4(0.f,0.f,0.f,0.f), a01 = make_float4(0.f,0.f,0.f,0.f);
    float4 a10 = make_float4(0.f,0.f,0.f,0.f), a11 = make_float4(0.f,0.f,0.f,0.f);
    #pragma unroll
    for (int c = 0; c < C_IN; ++c) {
        const float4 wv = *reinterpret_cast<const float4*>(&w[c * EMBED + e4 * 4]);
        const float p00 = pooled[c][lr * 2 + 0];
        const float p01 = pooled[c][lr * 2 + 1];
        const float p10 = pooled[c][4 + lr * 2 + 0];
        const float p11 = pooled[c][4 + lr * 2 + 1];
        a00.x = fmaf(p00, wv.x, a00.x);  a01.x = fmaf(p01, wv.x, a01.x);
        a10.x = fmaf(p10, wv.x, a10.x);  a11.x = fmaf(p11, wv.x, a11.x);
        a00.y = fmaf(p00, wv.y, a00.y);  a01.y = fmaf(p01, wv.y, a01.y);
        a10.y = fmaf(p10, wv.y, a10.y);  a11.y = fmaf(p11, wv.y, a11.y);
        a00.z = fmaf(p00, wv.z, a00.z);  a01.z = fmaf(p01, wv.z, a01.z);
        a10.z = fmaf(p10, wv.z, a10.z);  a11.z = fmaf(p11, wv.z, a11.z);
        a00.w = fmaf(p00, wv.w, a00.w);  a01.w = fmaf(p01, wv.w, a01.w);
        a10.w = fmaf(p10, wv.w, a10.w);  a11.w = fmaf(p11, wv.w, a11.w);
    }

    const int pi = pr * 2 + lr;
    const int pj = pp * 2;
    float* o0 = out + ((size_t)(2 * bz)     * (NP * NP) + (size_t)pi * NP + pj) * EMBED + e4 * 4;
    float* o1 = out + ((size_t)(2 * bz + 1) * (NP * NP) + (size_t)pi * NP + pj) * EMBED + e4 * 4;
    *reinterpret_cast<float4*>(o0)         = a00;
    *reinterpret_cast<float4*>(o0 + EMBED) = a01;
    *reinterpret_cast<float4*>(o1)         = a10;
    *reinterpret_cast<float4*>(o1 + EMBED) = a11;
}

extern "C" void kernel_launch(void* const* d_in, const int* in_sizes, int n_in,
                              void* d_out, int out_size)
{
    const float* x = (const float*)d_in[0];
    const float* w = (const float*)d_in[1];
    float* out = (float*)d_out;

    dim3 grid(7, 7, 32);   // 1568 CTAs
    patch_block2_kernel<<<grid, NTH>>>(x, w, out);
}